// round 4
// baseline (speedup 1.0000x reference)
#include <cuda_runtime.h>
#include <cuda_bf16.h>
#include <cstdint>

// Problem constants (fixed per dataset)
#define NN 100000
#define EE 1600000
#define DD 128

// Static device scratch (runtime allocs are forbidden)
__device__ float g_xw[(size_t)NN * DD];   // x @ W
__device__ float g_deg[NN];
__device__ float g_dinv[NN];
__device__ int   g_cnt[NN];               // edges per target
__device__ int   g_off[NN];               // bucket start
__device__ int   g_pos[NN];               // bucket fill cursor
__device__ int   g_src[EE];               // bucketed source node ids
__device__ float g_w[EE];                 // bucketed normalized edge weights
__device__ int   g_total;
__device__ int   g_is64;                  // edge_index dtype flag

// ---------------------------------------------------------------------------
// Kd: detect edge_index dtype. int64 little-endian with ids < 2^32 has all
// odd int32 words == 0; int32 random ids make that essentially impossible.
__global__ void k_detect(const int* __restrict__ ei32) {
    int nz = 0;
#pragma unroll
    for (int j = 1; j < 128; j += 2) nz |= ei32[j];
    g_is64 = (nz == 0) ? 1 : 0;
}

__device__ __forceinline__ int load_idx(const void* ei, size_t pos) {
    if (g_is64) return (int)((const long long*)ei)[pos];
    return ((const int*)ei)[pos];
}

// ---------------------------------------------------------------------------
// K0: reset per-call state; deg starts at 1.0 (self-loop weight)
__global__ void k_reset(int n) {
    int i = blockIdx.x * blockDim.x + threadIdx.x;
    if (i < n) { g_deg[i] = 1.0f; g_cnt[i] = 0; }
    if (i == 0) g_total = 0;
}

// K1: accumulate edge weights + edge counts at targets
__global__ void k_deg_edges(const void* __restrict__ ei,
                            const float* __restrict__ ew, int E) {
    int e = blockIdx.x * blockDim.x + threadIdx.x;
    if (e < E) {
        int c = load_idx(ei, (size_t)E + e);  // col = target
        atomicAdd(&g_deg[c], ew[e]);
        atomicAdd(&g_cnt[c], 1);
    }
}

// K2: dinv = rsqrt(deg); assign disjoint bucket offsets
__global__ void k_dinv_off(int n) {
    int i = blockIdx.x * blockDim.x + threadIdx.x;
    if (i < n) {
        float d = g_deg[i];
        g_dinv[i] = (d > 0.0f) ? rsqrtf(d) : 0.0f;
        int o = atomicAdd(&g_total, g_cnt[i]);
        g_off[i] = o;
        g_pos[i] = o;
    }
}

// ---------------------------------------------------------------------------
// K3: xw = x @ W  (fp32 SIMT, 64-row tile, K chunked by 32)
__global__ __launch_bounds__(256) void k_gemm(
    const float* __restrict__ x, const float* __restrict__ w, int n)
{
    __shared__ float ws[32][128];
    __shared__ float xs[64][32];

    int tid = threadIdx.x;
    int tx = tid & 31;        // output cols tx*4 .. tx*4+3
    int ty = tid >> 5;        // rows ty*8 .. ty*8+7
    int row0 = blockIdx.x * 64;

    float acc[8][4];
#pragma unroll
    for (int r = 0; r < 8; r++)
#pragma unroll
        for (int c = 0; c < 4; c++) acc[r][c] = 0.0f;

    for (int kc = 0; kc < 128; kc += 32) {
#pragma unroll
        for (int i = tid; i < 32 * 128; i += 256) {
            int kk = i >> 7, cc = i & 127;
            ws[kk][cc] = w[(size_t)(kc + kk) * 128 + cc];
        }
#pragma unroll
        for (int i = tid; i < 64 * 32; i += 256) {
            int rr = i >> 5, kk = i & 31;
            int gr = row0 + rr;
            xs[rr][kk] = (gr < n) ? x[(size_t)gr * 128 + kc + kk] : 0.0f;
        }
        __syncthreads();

#pragma unroll
        for (int k = 0; k < 32; k++) {
            float4 wv = *(const float4*)&ws[k][tx * 4];
#pragma unroll
            for (int r = 0; r < 8; r++) {
                float xv = xs[ty * 8 + r][k];
                acc[r][0] = fmaf(xv, wv.x, acc[r][0]);
                acc[r][1] = fmaf(xv, wv.y, acc[r][1]);
                acc[r][2] = fmaf(xv, wv.z, acc[r][2]);
                acc[r][3] = fmaf(xv, wv.w, acc[r][3]);
            }
        }
        __syncthreads();
    }

#pragma unroll
    for (int r = 0; r < 8; r++) {
        int gr = row0 + ty * 8 + r;
        if (gr < n) {
            float4 v = make_float4(acc[r][0], acc[r][1], acc[r][2], acc[r][3]);
            *(float4*)&g_xw[(size_t)gr * 128 + tx * 4] = v;
        }
    }
}

// ---------------------------------------------------------------------------
// K4: bucket placement — per edge, drop (src, norm) into target's segment
__global__ void k_place(const void* __restrict__ ei,
                        const float* __restrict__ ew, int E) {
    int e = blockIdx.x * blockDim.x + threadIdx.x;
    if (e < E) {
        int r = load_idx(ei, e);
        int c = load_idx(ei, (size_t)E + e);
        float norm = g_dinv[r] * ew[e] * g_dinv[c];
        int p = atomicAdd(&g_pos[c], 1);
        g_src[p] = r;
        g_w[p]   = norm;
    }
}

// ---------------------------------------------------------------------------
// K5: gather-aggregate per target node; fuse self-loop + bias + PReLU
__global__ __launch_bounds__(128) void k_gather(
    const float* __restrict__ bias, const float* __restrict__ pa,
    float* __restrict__ out, int n)
{
    int i = blockIdx.x;
    if (i >= n) return;
    int tid = threadIdx.x;

    __shared__ int   ss[128];
    __shared__ float sw[128];

    int off = g_off[i];
    int cnt = g_cnt[i];
    float di = g_dinv[i];

    // self-loop term: dinv_i * 1.0 * dinv_i * xw_i
    float acc = di * di * g_xw[(size_t)i * DD + tid];

    for (int base = 0; base < cnt; base += 128) {
        int m = min(128, cnt - base);
        if (tid < m) {
            ss[tid] = g_src[off + base + tid];
            sw[tid] = g_w[off + base + tid];
        }
        __syncthreads();
#pragma unroll 4
        for (int j = 0; j < m; j++) {
            acc += sw[j] * g_xw[(size_t)ss[j] * DD + tid];
        }
        __syncthreads();
    }

    float o = acc + bias[tid];
    float slope = pa[0];
    out[(size_t)i * DD + tid] = (o >= 0.0f) ? o : slope * o;
}

// ---------------------------------------------------------------------------
extern "C" void kernel_launch(void* const* d_in, const int* in_sizes, int n_in,
                              void* d_out, int out_size)
{
    const float* x    = (const float*)d_in[0];
    const void*  ei   = d_in[1];
    const float* ew   = (const float*)d_in[2];
    const float* w    = (const float*)d_in[3];
    const float* bias = (const float*)d_in[4];
    const float* pa   = (const float*)d_in[5];
    float* out = (float*)d_out;

    int n = in_sizes[0] / DD;
    int E = in_sizes[2];

    k_detect<<<1, 1>>>((const int*)ei);
    k_reset<<<(n + 255) / 256, 256>>>(n);
    k_deg_edges<<<(E + 255) / 256, 256>>>(ei, ew, E);
    k_dinv_off<<<(n + 255) / 256, 256>>>(n);
    k_gemm<<<(n + 63) / 64, 256>>>(x, w, n);
    k_place<<<(E + 255) / 256, 256>>>(ei, ew, E);
    k_gather<<<n, 128>>>(bias, pa, out, n);
}

// round 7
// speedup vs baseline: 1.8049x; 1.8049x over previous
#include <cuda_runtime.h>
#include <cuda_bf16.h>
#include <cstdint>

// Problem constants (fixed per dataset)
#define NN 100000
#define EE 1600000
#define DD 128

// Static device scratch (runtime allocs are forbidden)
__device__ float g_xw[(size_t)NN * DD];   // x @ W
__device__ float g_deg[NN];
__device__ float g_dinv[NN];
__device__ int   g_cnt[NN];               // edges per target
__device__ int   g_off[NN];               // bucket start
__device__ int   g_pos[NN];               // bucket fill cursor
__device__ int   g_src[EE];               // bucketed source node ids
__device__ float g_w[EE];                 // bucketed normalized edge weights
__device__ int   g_total;
__device__ int   g_is64;                  // edge_index dtype flag

__device__ __forceinline__ int load_idx(const void* ei, size_t pos) {
    if (g_is64) return (int)((const long long*)ei)[pos];
    return ((const int*)ei)[pos];
}

// ---------------------------------------------------------------------------
// K0: reset per-call state; deg starts at 1.0 (self-loop weight).
// Thread 0 of block 0 also detects the edge_index dtype: int64 little-endian
// with ids < 2^32 has all odd int32 words == 0.
__global__ void k_reset(const int* __restrict__ ei32, int n) {
    int i = blockIdx.x * blockDim.x + threadIdx.x;
    if (i < n) { g_deg[i] = 1.0f; g_cnt[i] = 0; }
    if (i == 0) {
        g_total = 0;
        int nz = 0;
#pragma unroll
        for (int j = 1; j < 128; j += 2) nz |= ei32[j];
        g_is64 = (nz == 0) ? 1 : 0;
    }
}

// K1: accumulate edge weights + edge counts at targets
__global__ void k_deg_edges(const void* __restrict__ ei,
                            const float* __restrict__ ew, int E) {
    int e = blockIdx.x * blockDim.x + threadIdx.x;
    if (e < E) {
        int c = load_idx(ei, (size_t)E + e);  // col = target
        atomicAdd(&g_deg[c], ew[e]);
        atomicAdd(&g_cnt[c], 1);
    }
}

// K2: dinv = rsqrt(deg); assign disjoint bucket offsets
__global__ void k_dinv_off(int n) {
    int i = blockIdx.x * blockDim.x + threadIdx.x;
    if (i < n) {
        float d = g_deg[i];
        g_dinv[i] = (d > 0.0f) ? rsqrtf(d) : 0.0f;
        int o = atomicAdd(&g_total, g_cnt[i]);
        g_off[i] = o;
        g_pos[i] = o;
    }
}

// ---------------------------------------------------------------------------
// K3: xw = x @ W  (fp32 SIMT, 64-row tile, K chunked by 32)
__global__ __launch_bounds__(256) void k_gemm(
    const float* __restrict__ x, const float* __restrict__ w, int n)
{
    __shared__ float ws[32][128];
    __shared__ float xs[64][32];

    int tid = threadIdx.x;
    int tx = tid & 31;        // output cols tx*4 .. tx*4+3
    int ty = tid >> 5;        // rows ty*8 .. ty*8+7
    int row0 = blockIdx.x * 64;

    float acc[8][4];
#pragma unroll
    for (int r = 0; r < 8; r++)
#pragma unroll
        for (int c = 0; c < 4; c++) acc[r][c] = 0.0f;

    for (int kc = 0; kc < 128; kc += 32) {
#pragma unroll
        for (int i = tid; i < 32 * 128; i += 256) {
            int kk = i >> 7, cc = i & 127;
            ws[kk][cc] = w[(size_t)(kc + kk) * 128 + cc];
        }
#pragma unroll
        for (int i = tid; i < 64 * 32; i += 256) {
            int rr = i >> 5, kk = i & 31;
            int gr = row0 + rr;
            xs[rr][kk] = (gr < n) ? x[(size_t)gr * 128 + kc + kk] : 0.0f;
        }
        __syncthreads();

#pragma unroll
        for (int k = 0; k < 32; k++) {
            float4 wv = *(const float4*)&ws[k][tx * 4];
#pragma unroll
            for (int r = 0; r < 8; r++) {
                float xv = xs[ty * 8 + r][k];
                acc[r][0] = fmaf(xv, wv.x, acc[r][0]);
                acc[r][1] = fmaf(xv, wv.y, acc[r][1]);
                acc[r][2] = fmaf(xv, wv.z, acc[r][2]);
                acc[r][3] = fmaf(xv, wv.w, acc[r][3]);
            }
        }
        __syncthreads();
    }

#pragma unroll
    for (int r = 0; r < 8; r++) {
        int gr = row0 + ty * 8 + r;
        if (gr < n) {
            float4 v = make_float4(acc[r][0], acc[r][1], acc[r][2], acc[r][3]);
            *(float4*)&g_xw[(size_t)gr * 128 + tx * 4] = v;
        }
    }
}

// ---------------------------------------------------------------------------
// K4: bucket placement — per edge, drop (src, norm) into target's segment
__global__ void k_place(const void* __restrict__ ei,
                        const float* __restrict__ ew, int E) {
    int e = blockIdx.x * blockDim.x + threadIdx.x;
    if (e < E) {
        int r = load_idx(ei, e);
        int c = load_idx(ei, (size_t)E + e);
        float norm = g_dinv[r] * ew[e] * g_dinv[c];
        int p = atomicAdd(&g_pos[c], 1);
        g_src[p] = r;
        g_w[p]   = norm;
    }
}

// ---------------------------------------------------------------------------
// K5: warp-per-node gather-aggregate; fuse self-loop + bias + PReLU.
// Each lane owns features [lane*4, lane*4+4) as a float4.
__global__ __launch_bounds__(256) void k_gather(
    const float* __restrict__ bias, const float* __restrict__ pa,
    float* __restrict__ out, int n)
{
    int wid = (blockIdx.x * blockDim.x + threadIdx.x) >> 5;
    if (wid >= n) return;
    int lane = threadIdx.x & 31;
    int i = wid;

    int off = g_off[i];
    int cnt = g_cnt[i];
    float di = g_dinv[i];
    float s = di * di;

    // self-loop term
    float4 v = *(const float4*)&g_xw[(size_t)i * DD + lane * 4];
    float4 acc = make_float4(s * v.x, s * v.y, s * v.z, s * v.w);

#pragma unroll 4
    for (int j = 0; j < cnt; j++) {
        int   sj = __ldg(&g_src[off + j]);   // uniform across warp -> broadcast
        float wj = __ldg(&g_w[off + j]);
        float4 r = *(const float4*)&g_xw[(size_t)sj * DD + lane * 4];
        acc.x = fmaf(wj, r.x, acc.x);
        acc.y = fmaf(wj, r.y, acc.y);
        acc.z = fmaf(wj, r.z, acc.z);
        acc.w = fmaf(wj, r.w, acc.w);
    }

    float4 bv = *(const float4*)&bias[lane * 4];
    float slope = pa[0];
    float4 o;
    o.x = acc.x + bv.x; o.x = (o.x >= 0.0f) ? o.x : slope * o.x;
    o.y = acc.y + bv.y; o.y = (o.y >= 0.0f) ? o.y : slope * o.y;
    o.z = acc.z + bv.z; o.z = (o.z >= 0.0f) ? o.z : slope * o.z;
    o.w = acc.w + bv.w; o.w = (o.w >= 0.0f) ? o.w : slope * o.w;
    *(float4*)&out[(size_t)i * DD + lane * 4] = o;
}

// ---------------------------------------------------------------------------
extern "C" void kernel_launch(void* const* d_in, const int* in_sizes, int n_in,
                              void* d_out, int out_size)
{
    const float* x    = (const float*)d_in[0];
    const void*  ei   = d_in[1];
    const float* ew   = (const float*)d_in[2];
    const float* w    = (const float*)d_in[3];
    const float* bias = (const float*)d_in[4];
    const float* pa   = (const float*)d_in[5];
    float* out = (float*)d_out;

    int n = in_sizes[0] / DD;
    int E = in_sizes[2];

    k_reset<<<(n + 255) / 256, 256>>>((const int*)ei, n);
    k_deg_edges<<<(E + 255) / 256, 256>>>(ei, ew, E);
    k_dinv_off<<<(n + 255) / 256, 256>>>(n);
    k_gemm<<<(n + 63) / 64, 256>>>(x, w, n);
    k_place<<<(E + 255) / 256, 256>>>(ei, ew, E);
    // warp per node, 8 warps (256 threads) per block
    k_gather<<<(n + 7) / 8, 256>>>(bias, pa, out, n);
}

// round 13
// speedup vs baseline: 2.2585x; 1.2513x over previous
#include <cuda_runtime.h>
#include <cuda_bf16.h>
#include <cstdint>

// Problem constants (fixed per dataset)
#define NN 100000
#define EE 1600000
#define DD 128

// Static device scratch (runtime allocs are forbidden)
__device__ float g_xw[(size_t)NN * DD];   // x @ W
__device__ float g_deg[NN];
__device__ float g_dinv[NN];
__device__ int   g_cnt[NN];               // edges per target
__device__ int   g_off[NN];               // bucket start
__device__ int   g_pos[NN];               // bucket fill cursor
__device__ int   g_src[EE];               // bucketed source node ids
__device__ float g_w[EE];                 // bucketed normalized edge weights
__device__ int   g_total;
__device__ int   g_is64;                  // edge_index dtype flag

__device__ __forceinline__ int load_idx(const void* ei, size_t pos) {
    if (g_is64) return (int)((const long long*)ei)[pos];
    return ((const int*)ei)[pos];
}

__device__ __forceinline__ float to_tf32(float f) {
    float r;
    asm("cvt.rna.tf32.f32 %0, %1;" : "=f"(r) : "f"(f));
    return r;
}

// ---------------------------------------------------------------------------
// K0: reset; deg=1 (self-loop); thread 0 detects edge_index dtype
__global__ void k_reset(const int* __restrict__ ei32, int n) {
    int i = blockIdx.x * blockDim.x + threadIdx.x;
    if (i < n) { g_deg[i] = 1.0f; g_cnt[i] = 0; }
    if (i == 0) {
        g_total = 0;
        int nz = 0;
#pragma unroll
        for (int j = 1; j < 128; j += 2) nz |= ei32[j];
        g_is64 = (nz == 0) ? 1 : 0;
    }
}

// K1: accumulate edge weights + counts at targets
__global__ void k_deg_edges(const void* __restrict__ ei,
                            const float* __restrict__ ew, int E) {
    int e = blockIdx.x * blockDim.x + threadIdx.x;
    if (e < E) {
        int c = load_idx(ei, (size_t)E + e);
        atomicAdd(&g_deg[c], ew[e]);
        atomicAdd(&g_cnt[c], 1);
    }
}

// K2: dinv = rsqrt(deg); disjoint bucket offsets
__global__ void k_dinv_off(int n) {
    int i = blockIdx.x * blockDim.x + threadIdx.x;
    if (i < n) {
        float d = g_deg[i];
        g_dinv[i] = (d > 0.0f) ? rsqrtf(d) : 0.0f;
        int o = atomicAdd(&g_total, g_cnt[i]);
        g_off[i] = o;
        g_pos[i] = o;
    }
}

// ---------------------------------------------------------------------------
// K3: xw = x @ W via mma.sync tf32 (m16n8k8), 128x128x128 per CTA, 512 thr.
// Warp w: rows [(w>>1)*16, +16), cols [(w&1)*64, +64)  -> acc[8][4]
// smem: x tile [128][132] f32 (tf32-rounded bits), W tile [128][132]
#define PITCH 132
#define SM_XT 0
#define SM_WT (128 * PITCH)
#define SM_FLOATS (2 * 128 * PITCH)
#define SM_BYTES (SM_FLOATS * 4)

__global__ __launch_bounds__(512) void k_gemm_mma(
    const float* __restrict__ x, const float* __restrict__ w, int n)
{
    extern __shared__ float sf[];
    float* xs = sf + SM_XT;
    float* ws = sf + SM_WT;

    int tid = threadIdx.x;
    int wid = tid >> 5;
    int lane = tid & 31;
    int gid = lane >> 2;     // group id 0..7
    int tid4 = lane & 3;     // thread-in-group 0..3
    int row0 = blockIdx.x * 128;

    // Load x tile (coalesced float4, tf32-round into smem)
    const float4 z4 = make_float4(0.f, 0.f, 0.f, 0.f);
#pragma unroll
    for (int f = tid; f < 4096; f += 512) {
        int row = f >> 5;
        int c4  = f & 31;
        int gr = row0 + row;
        float4 v = (gr < n) ? *(const float4*)&x[(size_t)gr * 128 + c4 * 4] : z4;
        float* p = &xs[row * PITCH + c4 * 4];
        p[0] = to_tf32(v.x); p[1] = to_tf32(v.y);
        p[2] = to_tf32(v.z); p[3] = to_tf32(v.w);
    }
    // Load W tile [k][n]
#pragma unroll
    for (int f = tid; f < 4096; f += 512) {
        int k  = f >> 5;
        int c4 = f & 31;
        float4 v = *(const float4*)&w[(size_t)k * 128 + c4 * 4];
        float* p = &ws[k * PITCH + c4 * 4];
        p[0] = to_tf32(v.x); p[1] = to_tf32(v.y);
        p[2] = to_tf32(v.z); p[3] = to_tf32(v.w);
    }
    __syncthreads();

    int mrow  = (wid >> 1) * 16;
    int nhalf = (wid & 1) * 64;

    float acc[8][4];
#pragma unroll
    for (int na = 0; na < 8; na++)
#pragma unroll
        for (int q = 0; q < 4; q++) acc[na][q] = 0.0f;

#pragma unroll
    for (int ks = 0; ks < 16; ks++) {
        int k0 = ks * 8;
        // A fragment (m16 x k8), row-major
        uint32_t a0 = __float_as_uint(xs[(mrow + gid)     * PITCH + k0 + tid4]);
        uint32_t a1 = __float_as_uint(xs[(mrow + gid + 8) * PITCH + k0 + tid4]);
        uint32_t a2 = __float_as_uint(xs[(mrow + gid)     * PITCH + k0 + tid4 + 4]);
        uint32_t a3 = __float_as_uint(xs[(mrow + gid + 8) * PITCH + k0 + tid4 + 4]);
#pragma unroll
        for (int na = 0; na < 8; na++) {
            int ncol = nhalf + na * 8 + gid;
            uint32_t b0 = __float_as_uint(ws[(k0 + tid4)     * PITCH + ncol]);
            uint32_t b1 = __float_as_uint(ws[(k0 + tid4 + 4) * PITCH + ncol]);
            asm volatile(
                "mma.sync.aligned.m16n8k8.row.col.f32.tf32.tf32.f32 "
                "{%0,%1,%2,%3}, {%4,%5,%6,%7}, {%8,%9}, {%0,%1,%2,%3};"
                : "+f"(acc[na][0]), "+f"(acc[na][1]),
                  "+f"(acc[na][2]), "+f"(acc[na][3])
                : "r"(a0), "r"(a1), "r"(a2), "r"(a3), "r"(b0), "r"(b1));
        }
    }

    // Epilogue: d-frag c0,c1 at (gid, tid4*2), c2,c3 at (gid+8, tid4*2)
    int gr0 = row0 + mrow + gid;
    int gr1 = gr0 + 8;
#pragma unroll
    for (int na = 0; na < 8; na++) {
        int col = nhalf + na * 8 + tid4 * 2;
        if (gr0 < n)
            *(float2*)&g_xw[(size_t)gr0 * 128 + col] =
                make_float2(acc[na][0], acc[na][1]);
        if (gr1 < n)
            *(float2*)&g_xw[(size_t)gr1 * 128 + col] =
                make_float2(acc[na][2], acc[na][3]);
    }
}

// ---------------------------------------------------------------------------
// K4: bucket placement
__global__ void k_place(const void* __restrict__ ei,
                        const float* __restrict__ ew, int E) {
    int e = blockIdx.x * blockDim.x + threadIdx.x;
    if (e < E) {
        int r = load_idx(ei, e);
        int c = load_idx(ei, (size_t)E + e);
        float norm = g_dinv[r] * ew[e] * g_dinv[c];
        int p = atomicAdd(&g_pos[c], 1);
        g_src[p] = r;
        g_w[p]   = norm;
    }
}

// ---------------------------------------------------------------------------
// K5: warp-per-node gather-aggregate; fuse self-loop + bias + PReLU
__global__ __launch_bounds__(256) void k_gather(
    const float* __restrict__ bias, const float* __restrict__ pa,
    float* __restrict__ out, int n)
{
    int wid = (blockIdx.x * blockDim.x + threadIdx.x) >> 5;
    if (wid >= n) return;
    int lane = threadIdx.x & 31;
    int i = wid;

    int off = g_off[i];
    int cnt = g_cnt[i];
    float di = g_dinv[i];
    float s = di * di;

    float4 v = *(const float4*)&g_xw[(size_t)i * DD + lane * 4];
    float4 acc = make_float4(s * v.x, s * v.y, s * v.z, s * v.w);

#pragma unroll 4
    for (int j = 0; j < cnt; j++) {
        int   sj = __ldg(&g_src[off + j]);
        float wj = __ldg(&g_w[off + j]);
        float4 r = *(const float4*)&g_xw[(size_t)sj * DD + lane * 4];
        acc.x = fmaf(wj, r.x, acc.x);
        acc.y = fmaf(wj, r.y, acc.y);
        acc.z = fmaf(wj, r.z, acc.z);
        acc.w = fmaf(wj, r.w, acc.w);
    }

    float4 bv = *(const float4*)&bias[lane * 4];
    float slope = pa[0];
    float4 o;
    o.x = acc.x + bv.x; o.x = (o.x >= 0.0f) ? o.x : slope * o.x;
    o.y = acc.y + bv.y; o.y = (o.y >= 0.0f) ? o.y : slope * o.y;
    o.z = acc.z + bv.z; o.z = (o.z >= 0.0f) ? o.z : slope * o.z;
    o.w = acc.w + bv.w; o.w = (o.w >= 0.0f) ? o.w : slope * o.w;
    *(float4*)&out[(size_t)i * DD + lane * 4] = o;
}

// ---------------------------------------------------------------------------
extern "C" void kernel_launch(void* const* d_in, const int* in_sizes, int n_in,
                              void* d_out, int out_size)
{
    const float* x    = (const float*)d_in[0];
    const void*  ei   = d_in[1];
    const float* ew   = (const float*)d_in[2];
    const float* w    = (const float*)d_in[3];
    const float* bias = (const float*)d_in[4];
    const float* pa   = (const float*)d_in[5];
    float* out = (float*)d_out;

    int n = in_sizes[0] / DD;
    int E = in_sizes[2];

    cudaFuncSetAttribute(k_gemm_mma,
                         cudaFuncAttributeMaxDynamicSharedMemorySize, SM_BYTES);

    k_reset<<<(n + 255) / 256, 256>>>((const int*)ei, n);
    k_deg_edges<<<(E + 255) / 256, 256>>>(ei, ew, E);
    k_dinv_off<<<(n + 255) / 256, 256>>>(n);
    k_gemm_mma<<<(n + 127) / 128, 512, SM_BYTES>>>(x, w, n);
    k_place<<<(E + 255) / 256, 256>>>(ei, ew, E);
    k_gather<<<(n + 7) / 8, 256>>>(bias, pa, out, n);
}